// round 4
// baseline (speedup 1.0000x reference)
#include <cuda_runtime.h>
#include <cstdint>

// Problem constants
#define NN 32768          // B*K rows
#define DD 256            // embedding dim
#define EE 1024           // num embeddings
#define DECAY 0.99f
#define ONE_MINUS_DECAY 0.01f
#define EPSV 1e-5f
#define CAP 4096          // max rows kept per codebook bucket (overflow -> atomics)

// Output layout (concatenated f32):
#define OFF_ZQ   0
#define OFF_LOSS 8388608
#define OFF_IDX  8388609
#define OFF_CB   8421377
#define OFF_CS   8683521
#define OFF_ES   8684545

// -------- scratch --------
__device__ float g_csq[EE];
__device__ int   g_indices[NN];
__device__ int   g_count[EE];
__device__ int   g_rows[EE * CAP];
__device__ float g_batch_es[EE * DD];   // overflow-only scatter target
__device__ float g_loss;
__device__ float g_ncs[EE];
__device__ float g_n;

// -------- f32x2 helpers --------
__device__ __forceinline__ void fma2(unsigned long long& d, unsigned long long a, unsigned long long b) {
    asm("fma.rn.f32x2 %0, %1, %2, %0;" : "+l"(d) : "l"(a), "l"(b));
}
__device__ __forceinline__ float2 unpack2(unsigned long long v) {
    float2 r;
    asm("mov.b64 {%0, %1}, %2;" : "=f"(r.x), "=f"(r.y) : "l"(v));
    return r;
}
__device__ __forceinline__ void cpa16(uint32_t dst, const void* src) {
    asm volatile("cp.async.cg.shared.global [%0], [%1], 16;\n" :: "r"(dst), "l"(src));
}
__device__ __forceinline__ void cpa_commit() {
    asm volatile("cp.async.commit_group;\n" ::: "memory");
}
template <int N>
__device__ __forceinline__ void cpa_wait() {
    asm volatile("cp.async.wait_group %0;\n" :: "n"(N) : "memory");
}

// -------- K0: zero counters + overflow scratch --------
__global__ void zero_kernel() {
    int i = blockIdx.x * blockDim.x + threadIdx.x;
    g_batch_es[i] = 0.0f;
    if (i < EE) g_count[i] = 0;
    if (i == 0) g_loss = 0.0f;
}

// -------- K0b: codebook squared norms --------
__global__ void csq_kernel(const float* __restrict__ cb) {
    int e = blockIdx.x;
    int lane = threadIdx.x;
    const float4* row = (const float4*)(cb + (size_t)e * DD);
    float4 a = row[lane];
    float4 b = row[lane + 32];
    float s = a.x * a.x + a.y * a.y + a.z * a.z + a.w * a.w
            + b.x * b.x + b.y * b.y + b.z * b.z + b.w * b.w;
    #pragma unroll
    for (int off = 16; off > 0; off >>= 1)
        s += __shfl_xor_sync(0xFFFFFFFFu, s, off);
    if (lane == 0) g_csq[e] = s;
}

// -------- K1: fused distance GEMM + argmin --------
// grid 512 (row tiles of 64). 256 threads = 16(tx) x 16(ty).
// Thread tile: 4 rows (ty*4+r) x 4 cols (tx + 16*j). K-contiguous shared
// tiles, double-buffered cp.async, f32x2 accumulation along K.
#define TMD 64
#define TND 64
#define TKD 16
#define RL  20   // floats per k-row (16 data + 4 pad); 80B, 16B-aligned rows

__global__ __launch_bounds__(256, 2)
void dist_kernel(const float* __restrict__ z_e, const float* __restrict__ cb) {
    __shared__ __align__(16) float x_s[2][TMD][RL];
    __shared__ __align__(16) float c_s[2][TND][RL];
    __shared__ float csq_s[EE];

    const int tid = threadIdx.x;
    const int tx = tid & 15, ty = tid >> 4;
    const int row0 = blockIdx.x * TMD;

    for (int i = tid; i < EE; i += 256) csq_s[i] = g_csq[i];

    // per-thread cp.async assignment: one 16B chunk each for x and c per stage
    const int lrow = tid >> 2;
    const int lch  = (tid & 3) << 2;

    float bestv[4];
    int   besti[4];
    #pragma unroll
    for (int r = 0; r < 4; r++) { bestv[r] = 3.4e38f; besti[r] = 0; }

    unsigned long long acc[16];

    // prologue: issue stage 0
    {
        uint32_t xd = (uint32_t)__cvta_generic_to_shared(&x_s[0][lrow][lch]);
        uint32_t cd = (uint32_t)__cvta_generic_to_shared(&c_s[0][lrow][lch]);
        cpa16(xd, z_e + (size_t)(row0 + lrow) * DD + lch);
        cpa16(cd, cb  + (size_t)lrow * DD + lch);
        cpa_commit();
    }

    for (int s = 0; s < 256; s++) {
        const int kt = s & 15;
        const int et = s >> 4;
        const int buf = s & 1;

        if (s + 1 < 256) {
            const int ns = s + 1;
            const int nkt = ns & 15, net = ns >> 4, nbuf = ns & 1;
            uint32_t xd = (uint32_t)__cvta_generic_to_shared(&x_s[nbuf][lrow][lch]);
            uint32_t cd = (uint32_t)__cvta_generic_to_shared(&c_s[nbuf][lrow][lch]);
            cpa16(xd, z_e + (size_t)(row0 + lrow) * DD + nkt * TKD + lch);
            cpa16(cd, cb  + (size_t)(net * TND + lrow) * DD + nkt * TKD + lch);
            cpa_commit();
            cpa_wait<1>();
        } else {
            cpa_wait<0>();
        }
        __syncthreads();

        if (kt == 0) {
            #pragma unroll
            for (int a = 0; a < 16; a++) acc[a] = 0ull;
        }

        #pragma unroll
        for (int kq = 0; kq < 4; kq++) {
            ulonglong2 xa[4], ca[4];
            #pragma unroll
            for (int r = 0; r < 4; r++)
                xa[r] = *(const ulonglong2*)&x_s[buf][ty * 4 + r][kq * 4];
            #pragma unroll
            for (int j = 0; j < 4; j++)
                ca[j] = *(const ulonglong2*)&c_s[buf][tx + 16 * j][kq * 4];
            #pragma unroll
            for (int r = 0; r < 4; r++)
                #pragma unroll
                for (int j = 0; j < 4; j++) {
                    fma2(acc[r * 4 + j], xa[r].x, ca[j].x);
                    fma2(acc[r * 4 + j], xa[r].y, ca[j].y);
                }
        }

        if (kt == 15) {
            #pragma unroll
            for (int r = 0; r < 4; r++)
                #pragma unroll
                for (int j = 0; j < 4; j++) {
                    float2 d = unpack2(acc[r * 4 + j]);
                    int col = et * TND + tx + 16 * j;
                    float sc = csq_s[col] - 2.0f * (d.x + d.y);
                    if (sc < bestv[r]) { bestv[r] = sc; besti[r] = col; }
                }
        }
        __syncthreads();
    }

    // butterfly argmin over the 16 tx lanes (half-warp groups)
    #pragma unroll
    for (int r = 0; r < 4; r++) {
        float bv = bestv[r];
        int   bi = besti[r];
        #pragma unroll
        for (int off = 1; off < 16; off <<= 1) {
            float ov = __shfl_xor_sync(0xFFFFFFFFu, bv, off);
            int   oi = __shfl_xor_sync(0xFFFFFFFFu, bi, off);
            if (ov < bv || (ov == bv && oi < bi)) { bv = ov; bi = oi; }
        }
        if (tx == 0) g_indices[row0 + ty * 4 + r] = bi;
    }
}

// -------- K2a: gather z_q, loss, histogram + bucket lists --------
__global__ void gather_kernel(const float* __restrict__ z_e,
                              const float* __restrict__ cb,
                              float* __restrict__ out) {
    __shared__ float warp_loss[8];
    __shared__ int   warp_pos[8];
    const int warp = threadIdx.x >> 5;
    const int lane = threadIdx.x & 31;
    const int row = blockIdx.x * 8 + warp;

    const int idx = g_indices[row];
    if (lane == 0) {
        int pos = atomicAdd(&g_count[idx], 1);
        if (pos < CAP) g_rows[idx * CAP + pos] = row;
        warp_pos[warp] = pos;
        out[OFF_IDX + row] = (float)idx;
    }
    __syncwarp();
    const bool overflow = (warp_pos[warp] >= CAP);

    const float4* crow = (const float4*)(cb + (size_t)idx * DD);
    const float4* xrow = (const float4*)(z_e + (size_t)row * DD);
    float4* zqrow = (float4*)(out + OFF_ZQ + (size_t)row * DD);
    float* es = g_batch_es + (size_t)idx * DD;

    float lsum = 0.0f;
    #pragma unroll
    for (int j = 0; j < 2; j++) {
        int q = lane + j * 32;
        float4 c = crow[q];
        float4 x = xrow[q];
        float4 o;
        o.x = x.x + (c.x - x.x); o.y = x.y + (c.y - x.y);
        o.z = x.z + (c.z - x.z); o.w = x.w + (c.w - x.w);
        zqrow[q] = o;
        float dx = x.x - c.x, dy = x.y - c.y, dz = x.z - c.z, dw = x.w - c.w;
        lsum += dx * dx + dy * dy + dz * dz + dw * dw;
        if (overflow) {
            atomicAdd(&es[q * 4 + 0], x.x);
            atomicAdd(&es[q * 4 + 1], x.y);
            atomicAdd(&es[q * 4 + 2], x.z);
            atomicAdd(&es[q * 4 + 3], x.w);
        }
    }
    #pragma unroll
    for (int off = 16; off > 0; off >>= 1)
        lsum += __shfl_xor_sync(0xFFFFFFFFu, lsum, off);
    if (lane == 0) warp_loss[warp] = lsum;
    __syncthreads();
    if (threadIdx.x == 0) {
        float s = 0.0f;
        #pragma unroll
        for (int w = 0; w < 8; w++) s += warp_loss[w];
        atomicAdd(&g_loss, s);
    }
}

// -------- K3a: new_cluster_size, n, vq_loss --------
__global__ void fin1_kernel(const float* __restrict__ ema_cs, float* __restrict__ out) {
    __shared__ float red[1024];
    int t = threadIdx.x;
    float ncs = DECAY * ema_cs[t] + ONE_MINUS_DECAY * (float)g_count[t];
    out[OFF_CS + t] = ncs;
    g_ncs[t] = ncs;
    red[t] = ncs;
    __syncthreads();
    for (int s = 512; s > 0; s >>= 1) {
        if (t < s) red[t] += red[t + s];
        __syncthreads();
    }
    if (t == 0) {
        g_n = red[0];
        out[OFF_LOSS] = 0.5f * g_loss / 8388608.0f;
    }
}

// -------- K3b: per-bucket embed sums + EMA + codebook out --------
__global__ void bucket_kernel(const float* __restrict__ z_e,
                              const float* __restrict__ ema_es,
                              float* __restrict__ out) {
    const int e = blockIdx.x;
    const int t = threadIdx.x;
    int cnt = g_count[e];
    if (cnt > CAP) cnt = CAP;
    const int* rows = g_rows + (size_t)e * CAP;
    size_t base = (size_t)e * DD + t;

    // seed with overflow scatter (zero unless a bucket exceeded CAP)
    float acc = g_batch_es[base];
    for (int r = 0; r < cnt; r++)
        acc += z_e[(size_t)rows[r] * DD + t];

    float n = g_n;
    float sm = (g_ncs[e] + EPSV) / (n + (float)EE * EPSV) * n;
    float nes = DECAY * ema_es[base] + ONE_MINUS_DECAY * acc;
    out[OFF_ES + base] = nes;
    out[OFF_CB + base] = nes / sm;
}

extern "C" void kernel_launch(void* const* d_in, const int* in_sizes, int n_in,
                              void* d_out, int out_size) {
    const float* z_e    = (const float*)d_in[0];
    const float* cb     = (const float*)d_in[1];
    const float* ema_cs = (const float*)d_in[2];
    const float* ema_es = (const float*)d_in[3];
    float* out = (float*)d_out;

    zero_kernel<<<EE * DD / 256, 256>>>();
    csq_kernel<<<EE, 32>>>(cb);
    dist_kernel<<<NN / TMD, 256>>>(z_e, cb);
    gather_kernel<<<NN / 8, 256>>>(z_e, cb, out);
    fin1_kernel<<<1, 1024>>>(ema_cs, out);
    bucket_kernel<<<EE, DD>>>(z_e, ema_es, out);
}